// round 2
// baseline (speedup 1.0000x reference)
#include <cuda_runtime.h>

#define HIDDEN        2048
#define NUM_HEADS     16
#define HEAD_DIM      128
#define BLOCK_SZ      64
#define NUM_SEQS      64
#define MAX_SEQ_LEN   2048
#define MAX_BLOCKS    32
#define NUM_KV_BLOCKS 2048
#define SCALE_F       0.088388347648318447f   // 128^-0.5

// Scratch (no allocations allowed)
__device__ float g_q[NUM_SEQS * HIDDEN];
__device__ float g_attn[NUM_SEQS * HIDDEN];

// ---------------------------------------------------------------------------
// Small-M GEMM: C[64, 2048] = A[64, 2048] @ W[2048, >=2048 (ldw)] + bias[2048]
// Grid (16 col-tiles x 8 seq-groups), 128 threads. Each thread owns 1 output
// column for 8 sequence rows; activations staged in SMEM and read as
// conflict-free broadcasts.
// ---------------------------------------------------------------------------
__global__ __launch_bounds__(128)
void smallm_gemm_kernel(const float* __restrict__ A,
                        const float* __restrict__ W, int ldw,
                        const float* __restrict__ bias,
                        float* __restrict__ C) {
    __shared__ float As[8][32];

    const int tid = threadIdx.x;
    const int col = blockIdx.x * 128 + tid;      // 0..2047
    const int sg  = blockIdx.y;                  // seq group of 8

    float acc[8];
#pragma unroll
    for (int s = 0; s < 8; s++) acc[s] = 0.0f;

    for (int kt = 0; kt < HIDDEN; kt += 32) {
        // Stage A[sg*8 .. sg*8+7][kt .. kt+31]  (256 floats, 2 per thread)
        {
            int i0 = tid;          // 0..127
            int i1 = tid + 128;    // 128..255
            As[i0 >> 5][i0 & 31] = A[(size_t)(sg * 8 + (i0 >> 5)) * HIDDEN + kt + (i0 & 31)];
            As[i1 >> 5][i1 & 31] = A[(size_t)(sg * 8 + (i1 >> 5)) * HIDDEN + kt + (i1 & 31)];
        }
        __syncthreads();

#pragma unroll
        for (int kk = 0; kk < 32; kk++) {
            float w = W[(size_t)(kt + kk) * ldw + col];
#pragma unroll
            for (int s = 0; s < 8; s++)
                acc[s] = fmaf(As[s][kk], w, acc[s]);
        }
        __syncthreads();
    }

    float b = bias[col];
#pragma unroll
    for (int s = 0; s < 8; s++)
        C[(size_t)(sg * 8 + s) * HIDDEN + col] = acc[s] + b;
}

// ---------------------------------------------------------------------------
// Paged attention decode. Grid (seq=64, head=16), 128 threads (4 warps).
// Pass 1: warp-per-token q.k scores -> SMEM (+ running max)
// Pass 2: exp + sum (in SMEM)
// Pass 3: warp-per-token weighted V accumulation (float4 per lane),
//         cross-warp combine in SMEM.
// Every K/V token is read once as one coalesced 512B transaction.
// ---------------------------------------------------------------------------
__global__ __launch_bounds__(128)
void paged_attn_kernel(const float* __restrict__ q,
                       const float* __restrict__ kv,
                       const int*   __restrict__ block_tables,
                       const int*   __restrict__ seq_lens,
                       float* __restrict__ out) {
    const int seq  = blockIdx.x;
    const int head = blockIdx.y;
    const int tid  = threadIdx.x;
    const int warp = tid >> 5;
    const int lane = tid & 31;

    __shared__ float s_scores[MAX_SEQ_LEN];
    __shared__ int   s_bt[MAX_BLOCKS];
    __shared__ float s_red[4];
    __shared__ float s_acc[4][HEAD_DIM];

    const int sl = seq_lens[seq];
    if (tid < MAX_BLOCKS)
        s_bt[tid] = block_tables[seq * MAX_BLOCKS + tid];
    __syncthreads();

    const float* K = kv;
    const float* V = kv + (size_t)NUM_KV_BLOCKS * BLOCK_SZ * HIDDEN;

    // q fragment: lane l holds dims 4l..4l+3 of this head's query
    const float4 qf = *(const float4*)(q + (size_t)seq * HIDDEN + head * HEAD_DIM + lane * 4);

    // ---- Pass 1: scores ----
    float wmax = -1e30f;
    for (int t = warp; t < sl; t += 4) {
        int phys = s_bt[t >> 6];
        const float* kp = K + ((size_t)phys * BLOCK_SZ + (t & 63)) * HIDDEN
                            + head * HEAD_DIM + lane * 4;
        float4 kf = *(const float4*)kp;
        float d = qf.x * kf.x + qf.y * kf.y + qf.z * kf.z + qf.w * kf.w;
#pragma unroll
        for (int o = 16; o; o >>= 1)
            d += __shfl_xor_sync(0xffffffffu, d, o);
        d *= SCALE_F;                  // same value on all lanes
        if (lane == 0) s_scores[t] = d;
        wmax = fmaxf(wmax, d);
    }
    if (lane == 0) s_red[warp] = wmax;
    __syncthreads();
    const float m = fmaxf(fmaxf(s_red[0], s_red[1]), fmaxf(s_red[2], s_red[3]));
    __syncthreads();   // everyone has read s_red before it is reused

    // ---- Pass 2: exp + sum ----
    float lsum = 0.0f;
    for (int t = tid; t < sl; t += 128) {
        float p = __expf(s_scores[t] - m);
        s_scores[t] = p;
        lsum += p;
    }
#pragma unroll
    for (int o = 16; o; o >>= 1)
        lsum += __shfl_xor_sync(0xffffffffu, lsum, o);
    __syncthreads();
    if (lane == 0) s_red[warp] = lsum;
    __syncthreads();
    const float inv = 1.0f / (s_red[0] + s_red[1] + s_red[2] + s_red[3]);

    // ---- Pass 3: weighted V ----
    float4 acc = make_float4(0.f, 0.f, 0.f, 0.f);
    for (int t = warp; t < sl; t += 4) {
        int phys = s_bt[t >> 6];
        const float* vp = V + ((size_t)phys * BLOCK_SZ + (t & 63)) * HIDDEN
                            + head * HEAD_DIM + lane * 4;
        float4 vf = *(const float4*)vp;
        float p = s_scores[t];
        acc.x = fmaf(p, vf.x, acc.x);
        acc.y = fmaf(p, vf.y, acc.y);
        acc.z = fmaf(p, vf.z, acc.z);
        acc.w = fmaf(p, vf.w, acc.w);
    }
    *(float4*)&s_acc[warp][lane * 4] = acc;
    __syncthreads();

    if (tid < HEAD_DIM) {
        float r = (s_acc[0][tid] + s_acc[1][tid] + s_acc[2][tid] + s_acc[3][tid]) * inv;
        out[(size_t)seq * HIDDEN + head * HEAD_DIM + tid] = r;
    }
}

// ---------------------------------------------------------------------------
extern "C" void kernel_launch(void* const* d_in, const int* in_sizes, int n_in,
                              void* d_out, int out_size) {
    const float* hs     = (const float*)d_in[0];
    const float* kv     = (const float*)d_in[1];
    const float* W_attn = (const float*)d_in[2];
    const float* b_attn = (const float*)d_in[3];
    const float* W_proj = (const float*)d_in[4];
    const float* b_proj = (const float*)d_in[5];
    const int*   bt     = (const int*)d_in[6];
    const int*   slen   = (const int*)d_in[7];
    float*       out    = (float*)d_out;

    float *qp = nullptr, *ap = nullptr;
    cudaGetSymbolAddress((void**)&qp, g_q);
    cudaGetSymbolAddress((void**)&ap, g_attn);

    dim3 gemm_grid(16, 8);
    // Q projection: only the first HIDDEN columns of W_attn are ever used.
    smallm_gemm_kernel<<<gemm_grid, 128>>>(hs, W_attn, 3 * HIDDEN, b_attn, qp);

    paged_attn_kernel<<<dim3(NUM_SEQS, NUM_HEADS), 128>>>(qp, kv, bt, slen, ap);

    smallm_gemm_kernel<<<gemm_grid, 128>>>(ap, W_proj, HIDDEN, b_proj, out);
}

// round 3
// speedup vs baseline: 3.2373x; 3.2373x over previous
#include <cuda_runtime.h>
#include <math.h>

#define HIDDEN        2048
#define NUM_HEADS     16
#define HEAD_DIM      128
#define BLOCK_SZ      64
#define NUM_SEQS      64
#define MAX_SEQ_LEN   2048
#define MAX_BLOCKS    32
#define NUM_KV_BLOCKS 2048
#define SCALE_F       0.088388347648318447f   // 128^-0.5

#define KCHUNKS       16     // split-K chunks (each 128 k)
#define KCHUNK_SZ     (HIDDEN / KCHUNKS)
#define SPLITS        4      // split-KV

// ---- static scratch (no allocations allowed) ----
__device__ float  g_q[NUM_SEQS * HIDDEN];
__device__ float  g_attn[NUM_SEQS * HIDDEN];
__device__ float  g_part[KCHUNKS * NUM_SEQS * HIDDEN];                 // GEMM split-K partials (8MB)
__device__ float  g_po[NUM_SEQS * NUM_HEADS * SPLITS * HEAD_DIM];      // attn partial outputs
__device__ float2 g_pml[NUM_SEQS * NUM_HEADS * SPLITS];                // attn partial (max, sum)

// ---------------------------------------------------------------------------
// Split-K GEMM: partial[kc][64, 2048] += A[64, kc-range] @ W[kc-range, 2048]
// grid (4 col-tiles, 8 seq-groups, 16 k-chunks) = 512 CTAs, 128 threads.
// Thread owns 4 consecutive cols (float4 W loads) x 8 seqs = 32 accumulators.
// ---------------------------------------------------------------------------
__global__ __launch_bounds__(128)
void gemm_splitk_kernel(const float* __restrict__ A,
                        const float* __restrict__ W, int ldw,
                        float* __restrict__ part) {
    __shared__ float As[8][32];

    const int tid = threadIdx.x;
    const int col = blockIdx.x * 512 + tid * 4;
    const int sg  = blockIdx.y;             // seqs sg*8 .. sg*8+7
    const int kc  = blockIdx.z;             // k range kc*128 .. +128

    float4 acc[8];
#pragma unroll
    for (int s = 0; s < 8; s++) acc[s] = make_float4(0.f, 0.f, 0.f, 0.f);

    const int kbeg = kc * KCHUNK_SZ;
    for (int kt = kbeg; kt < kbeg + KCHUNK_SZ; kt += 32) {
        // stage A[8 seqs][32 k]
        {
            int i0 = tid, i1 = tid + 128;
            As[i0 >> 5][i0 & 31] = A[(size_t)(sg * 8 + (i0 >> 5)) * HIDDEN + kt + (i0 & 31)];
            As[i1 >> 5][i1 & 31] = A[(size_t)(sg * 8 + (i1 >> 5)) * HIDDEN + kt + (i1 & 31)];
        }
        __syncthreads();

#pragma unroll
        for (int kk = 0; kk < 32; kk++) {
            const float4 w = *(const float4*)&W[(size_t)(kt + kk) * ldw + col];
#pragma unroll
            for (int s = 0; s < 8; s++) {
                float a = As[s][kk];
                acc[s].x = fmaf(a, w.x, acc[s].x);
                acc[s].y = fmaf(a, w.y, acc[s].y);
                acc[s].z = fmaf(a, w.z, acc[s].z);
                acc[s].w = fmaf(a, w.w, acc[s].w);
            }
        }
        __syncthreads();
    }

#pragma unroll
    for (int s = 0; s < 8; s++)
        *(float4*)&part[((size_t)kc * NUM_SEQS + sg * 8 + s) * HIDDEN + col] = acc[s];
}

// Reduce split-K partials + bias -> C[64, 2048]
__global__ __launch_bounds__(256)
void gemm_reduce_kernel(const float* __restrict__ part,
                        const float* __restrict__ bias,
                        float* __restrict__ C) {
    const int i = blockIdx.x * 256 + threadIdx.x;       // float4 index
    if (i >= NUM_SEQS * HIDDEN / 4) return;
    const int col4 = (i * 4) & (HIDDEN - 1);
    float4 s = *(const float4*)&bias[col4];
#pragma unroll
    for (int c = 0; c < KCHUNKS; c++) {
        const float4 p = *(const float4*)&part[(size_t)c * NUM_SEQS * HIDDEN + (size_t)i * 4];
        s.x += p.x; s.y += p.y; s.z += p.z; s.w += p.w;
    }
    *(float4*)&C[(size_t)i * 4] = s;
}

// ---------------------------------------------------------------------------
// Split-KV paged attention, partial pass.
// grid (64 seq, 16 head, 4 splits) = 4096 CTAs, 128 threads (4 warps).
// Each CTA handles a contiguous chunk of tokens; emits unnormalized
// (max, sum, acc[128]) for log-sum-exp combine.
// ---------------------------------------------------------------------------
__global__ __launch_bounds__(128)
void attn_partial_kernel(const float* __restrict__ q,
                         const float* __restrict__ kv,
                         const int*   __restrict__ block_tables,
                         const int*   __restrict__ seq_lens,
                         float*  __restrict__ part_o,
                         float2* __restrict__ part_ml) {
    const int seq   = blockIdx.x;
    const int head  = blockIdx.y;
    const int split = blockIdx.z;
    const int tid   = threadIdx.x;
    const int warp  = tid >> 5;
    const int lane  = tid & 31;
    const int pidx  = (seq * NUM_HEADS + head) * SPLITS + split;

    __shared__ float s_scores[MAX_SEQ_LEN / SPLITS];   // up to 512 tokens
    __shared__ int   s_bt[MAX_BLOCKS];
    __shared__ float s_red[4];
    __shared__ float s_acc[4][HEAD_DIM];

    const int sl    = seq_lens[seq];
    const int chunk = (sl + SPLITS - 1) / SPLITS;
    const int t0    = split * chunk;
    const int t1    = min(sl, t0 + chunk);
    const int n     = t1 - t0;

    if (n <= 0) {
        part_o[(size_t)pidx * HEAD_DIM + tid] = 0.0f;
        if (tid == 0) part_ml[pidx] = make_float2(-1e30f, 0.0f);
        return;
    }

    if (tid < MAX_BLOCKS)
        s_bt[tid] = block_tables[seq * MAX_BLOCKS + tid];
    __syncthreads();

    const float* K = kv;
    const float* V = kv + (size_t)NUM_KV_BLOCKS * BLOCK_SZ * HIDDEN;
    const size_t hoff = (size_t)head * HEAD_DIM + lane * 4;

    const float4 qf = *(const float4*)(q + (size_t)seq * HIDDEN + head * HEAD_DIM + lane * 4);

    // ---- Pass 1: scores (software-pipelined K loads) ----
    float wmax = -1e30f;
    {
        int t = t0 + warp;
        float4 kf = make_float4(0.f, 0.f, 0.f, 0.f);
        if (t < t1) {
            int phys = s_bt[t >> 6];
            kf = *(const float4*)(K + ((size_t)phys * BLOCK_SZ + (t & 63)) * HIDDEN + hoff);
        }
        for (; t < t1; t += 4) {
            const float4 cur = kf;
            const int tn = t + 4;
            if (tn < t1) {
                int phys = s_bt[tn >> 6];
                kf = *(const float4*)(K + ((size_t)phys * BLOCK_SZ + (tn & 63)) * HIDDEN + hoff);
            }
            float d = cur.x * qf.x + cur.y * qf.y + cur.z * qf.z + cur.w * qf.w;
#pragma unroll
            for (int o = 16; o; o >>= 1)
                d += __shfl_xor_sync(0xffffffffu, d, o);
            d *= SCALE_F;
            if (lane == 0) s_scores[t - t0] = d;
            wmax = fmaxf(wmax, d);
        }
    }
    if (lane == 0) s_red[warp] = wmax;
    __syncthreads();
    const float m = fmaxf(fmaxf(s_red[0], s_red[1]), fmaxf(s_red[2], s_red[3]));
    __syncthreads();

    // ---- Pass 2: exp + sum ----
    float lsum = 0.0f;
    for (int i = tid; i < n; i += 128) {
        float p = __expf(s_scores[i] - m);
        s_scores[i] = p;
        lsum += p;
    }
#pragma unroll
    for (int o = 16; o; o >>= 1)
        lsum += __shfl_xor_sync(0xffffffffu, lsum, o);
    if (lane == 0) s_red[warp] = lsum;
    __syncthreads();
    const float ltot = s_red[0] + s_red[1] + s_red[2] + s_red[3];

    // ---- Pass 3: weighted V (software-pipelined) ----
    float4 acc = make_float4(0.f, 0.f, 0.f, 0.f);
    {
        int t = t0 + warp;
        float4 vf = make_float4(0.f, 0.f, 0.f, 0.f);
        if (t < t1) {
            int phys = s_bt[t >> 6];
            vf = *(const float4*)(V + ((size_t)phys * BLOCK_SZ + (t & 63)) * HIDDEN + hoff);
        }
        for (; t < t1; t += 4) {
            const float4 cur = vf;
            const int tn = t + 4;
            if (tn < t1) {
                int phys = s_bt[tn >> 6];
                vf = *(const float4*)(V + ((size_t)phys * BLOCK_SZ + (tn & 63)) * HIDDEN + hoff);
            }
            const float p = s_scores[t - t0];
            acc.x = fmaf(p, cur.x, acc.x);
            acc.y = fmaf(p, cur.y, acc.y);
            acc.z = fmaf(p, cur.z, acc.z);
            acc.w = fmaf(p, cur.w, acc.w);
        }
    }
    *(float4*)&s_acc[warp][lane * 4] = acc;
    __syncthreads();

    // unnormalized partial accumulator + (m, l)
    part_o[(size_t)pidx * HEAD_DIM + tid] =
        s_acc[0][tid] + s_acc[1][tid] + s_acc[2][tid] + s_acc[3][tid];
    if (tid == 0) part_ml[pidx] = make_float2(m, ltot);
}

// Combine SPLITS partials via log-sum-exp. grid (64*16), 128 threads.
__global__ __launch_bounds__(128)
void attn_combine_kernel(const float*  __restrict__ part_o,
                         const float2* __restrict__ part_ml,
                         float* __restrict__ out) {
    const int sh  = blockIdx.x;          // seq*16 + head
    const int tid = threadIdx.x;         // dim

    float2 ml[SPLITS];
#pragma unroll
    for (int i = 0; i < SPLITS; i++) ml[i] = part_ml[sh * SPLITS + i];

    float M = -1e30f;
#pragma unroll
    for (int i = 0; i < SPLITS; i++) M = fmaxf(M, ml[i].x);

    float L = 0.0f, o = 0.0f;
#pragma unroll
    for (int i = 0; i < SPLITS; i++) {
        const float w = __expf(ml[i].x - M);
        L += w * ml[i].y;
        o = fmaf(w, part_o[(size_t)(sh * SPLITS + i) * HEAD_DIM + tid], o);
    }

    const int seq = sh >> 4, head = sh & 15;
    out[(size_t)seq * HIDDEN + head * HEAD_DIM + tid] = o / L;
}

// ---------------------------------------------------------------------------
extern "C" void kernel_launch(void* const* d_in, const int* in_sizes, int n_in,
                              void* d_out, int out_size) {
    const float* hs     = (const float*)d_in[0];
    const float* kv     = (const float*)d_in[1];
    const float* W_attn = (const float*)d_in[2];
    const float* b_attn = (const float*)d_in[3];
    const float* W_proj = (const float*)d_in[4];
    const float* b_proj = (const float*)d_in[5];
    const int*   bt     = (const int*)d_in[6];
    const int*   slen   = (const int*)d_in[7];
    float*       out    = (float*)d_out;

    float  *qp = nullptr, *ap = nullptr, *pp = nullptr, *po = nullptr;
    float2 *pml = nullptr;
    cudaGetSymbolAddress((void**)&qp,  g_q);
    cudaGetSymbolAddress((void**)&ap,  g_attn);
    cudaGetSymbolAddress((void**)&pp,  g_part);
    cudaGetSymbolAddress((void**)&po,  g_po);
    cudaGetSymbolAddress((void**)&pml, g_pml);

    const dim3 gemm_grid(HIDDEN / 512, NUM_SEQS / 8, KCHUNKS);
    const int  red_ctas = (NUM_SEQS * HIDDEN / 4 + 255) / 256;

    // Q projection (only first HIDDEN cols of W_attn are used)
    gemm_splitk_kernel<<<gemm_grid, 128>>>(hs, W_attn, 3 * HIDDEN, pp);
    gemm_reduce_kernel<<<red_ctas, 256>>>(pp, b_attn, qp);

    // Paged attention, split-KV
    attn_partial_kernel<<<dim3(NUM_SEQS, NUM_HEADS, SPLITS), 128>>>(qp, kv, bt, slen, po, pml);
    attn_combine_kernel<<<NUM_SEQS * NUM_HEADS, 128>>>(po, pml, ap);

    // Output projection
    gemm_splitk_kernel<<<gemm_grid, 128>>>(ap, W_proj, HIDDEN, pp);
    gemm_reduce_kernel<<<red_ctas, 256>>>(pp, b_proj, out);
}

// round 4
// speedup vs baseline: 4.2794x; 1.3219x over previous
#include <cuda_runtime.h>
#include <math.h>

#define HIDDEN        2048
#define NUM_HEADS     16
#define HEAD_DIM      128
#define BLOCK_SZ      64
#define NUM_SEQS      64
#define MAX_SEQ_LEN   2048
#define MAX_BLOCKS    32
#define NUM_KV_BLOCKS 2048
#define SCALE_F       0.088388347648318447f   // 128^-0.5

#define KCHUNKS       16     // split-K chunks (each 128 k)
#define KCHUNK_SZ     (HIDDEN / KCHUNKS)
#define SPLITS        8      // split-KV
#define CHUNK_MAX     (MAX_SEQ_LEN / SPLITS)   // 256

// ---- static scratch (no allocations allowed) ----
__device__ float  g_q[NUM_SEQS * HIDDEN];
__device__ float  g_attn[NUM_SEQS * HIDDEN];
__device__ float  g_part[KCHUNKS * NUM_SEQS * HIDDEN];                 // GEMM split-K partials
__device__ float  g_po[NUM_SEQS * NUM_HEADS * SPLITS * HEAD_DIM];      // attn partial outputs
__device__ float2 g_pml[NUM_SEQS * NUM_HEADS * SPLITS];                // attn partial (max, sum)

// ---------------------------------------------------------------------------
// Split-K GEMM: partial[kc][64, 2048] = A[64, kc-range] @ W[kc-range, 2048]
// ---------------------------------------------------------------------------
__global__ __launch_bounds__(128)
void gemm_splitk_kernel(const float* __restrict__ A,
                        const float* __restrict__ W, int ldw,
                        float* __restrict__ part) {
    __shared__ float As[8][32];

    const int tid = threadIdx.x;
    const int col = blockIdx.x * 512 + tid * 4;
    const int sg  = blockIdx.y;
    const int kc  = blockIdx.z;

    float4 acc[8];
#pragma unroll
    for (int s = 0; s < 8; s++) acc[s] = make_float4(0.f, 0.f, 0.f, 0.f);

    const int kbeg = kc * KCHUNK_SZ;
    for (int kt = kbeg; kt < kbeg + KCHUNK_SZ; kt += 32) {
        {
            int i0 = tid, i1 = tid + 128;
            As[i0 >> 5][i0 & 31] = A[(size_t)(sg * 8 + (i0 >> 5)) * HIDDEN + kt + (i0 & 31)];
            As[i1 >> 5][i1 & 31] = A[(size_t)(sg * 8 + (i1 >> 5)) * HIDDEN + kt + (i1 & 31)];
        }
        __syncthreads();

#pragma unroll
        for (int kk = 0; kk < 32; kk++) {
            const float4 w = *(const float4*)&W[(size_t)(kt + kk) * ldw + col];
#pragma unroll
            for (int s = 0; s < 8; s++) {
                float a = As[s][kk];
                acc[s].x = fmaf(a, w.x, acc[s].x);
                acc[s].y = fmaf(a, w.y, acc[s].y);
                acc[s].z = fmaf(a, w.z, acc[s].z);
                acc[s].w = fmaf(a, w.w, acc[s].w);
            }
        }
        __syncthreads();
    }

#pragma unroll
    for (int s = 0; s < 8; s++)
        *(float4*)&part[((size_t)kc * NUM_SEQS + sg * 8 + s) * HIDDEN + col] = acc[s];
}

// Reduce split-K partials + bias -> C[64, 2048]
__global__ __launch_bounds__(256)
void gemm_reduce_kernel(const float* __restrict__ part,
                        const float* __restrict__ bias,
                        float* __restrict__ C) {
    const int i = blockIdx.x * 256 + threadIdx.x;
    if (i >= NUM_SEQS * HIDDEN / 4) return;
    const int col4 = (i * 4) & (HIDDEN - 1);
    float4 s = *(const float4*)&bias[col4];
#pragma unroll
    for (int c = 0; c < KCHUNKS; c++) {
        const float4 p = *(const float4*)&part[(size_t)c * NUM_SEQS * HIDDEN + (size_t)i * 4];
        s.x += p.x; s.y += p.y; s.z += p.z; s.w += p.w;
    }
    *(float4*)&C[(size_t)i * 4] = s;
}

// ---------------------------------------------------------------------------
// Split-KV paged attention, partial pass.
// grid (64 seq, 16 head, 8 splits) = 8192 CTAs, 128 threads (4 warps).
// Token loop unrolled x4 per warp: 4 independent float4 loads in flight,
// 4 interleaved shuffle-reduce chains.
// ---------------------------------------------------------------------------
__global__ __launch_bounds__(128)
void attn_partial_kernel(const float* __restrict__ q,
                         const float* __restrict__ kv,
                         const int*   __restrict__ block_tables,
                         const int*   __restrict__ seq_lens,
                         float*  __restrict__ part_o,
                         float2* __restrict__ part_ml) {
    const int seq   = blockIdx.x;
    const int head  = blockIdx.y;
    const int split = blockIdx.z;
    const int tid   = threadIdx.x;
    const int warp  = tid >> 5;
    const int lane  = tid & 31;
    const int pidx  = (seq * NUM_HEADS + head) * SPLITS + split;

    __shared__ float s_scores[CHUNK_MAX];
    __shared__ int   s_bt[MAX_BLOCKS];
    __shared__ float s_red[4];
    __shared__ float s_acc[4][HEAD_DIM];

    const int sl    = seq_lens[seq];
    const int chunk = (sl + SPLITS - 1) / SPLITS;
    const int t0    = split * chunk;
    const int t1    = min(sl, t0 + chunk);
    const int n     = t1 - t0;

    if (n <= 0) {
        part_o[(size_t)pidx * HEAD_DIM + tid] = 0.0f;
        if (tid == 0) part_ml[pidx] = make_float2(-1e30f, 0.0f);
        return;
    }

    if (tid < MAX_BLOCKS)
        s_bt[tid] = block_tables[seq * MAX_BLOCKS + tid];
    __syncthreads();

    const float* K = kv;
    const float* V = kv + (size_t)NUM_KV_BLOCKS * BLOCK_SZ * HIDDEN;
    const size_t hoff = (size_t)head * HEAD_DIM + lane * 4;

    const float4 qf = *(const float4*)(q + (size_t)seq * HIDDEN + head * HEAD_DIM + lane * 4);

    // ---- Pass 1: scores, 4 tokens per warp per iteration ----
    float wmax = -1e30f;
    for (int tb = t0 + warp * 4; tb < t1; tb += 16) {
        float4 kf[4];
#pragma unroll
        for (int u = 0; u < 4; u++) {
            const int t = tb + u;
            if (t < t1) {
                const int phys = s_bt[t >> 6];
                kf[u] = *(const float4*)(K + ((size_t)phys * BLOCK_SZ + (t & 63)) * HIDDEN + hoff);
            } else {
                kf[u] = make_float4(0.f, 0.f, 0.f, 0.f);
            }
        }
        float d0 = kf[0].x * qf.x + kf[0].y * qf.y + kf[0].z * qf.z + kf[0].w * qf.w;
        float d1 = kf[1].x * qf.x + kf[1].y * qf.y + kf[1].z * qf.z + kf[1].w * qf.w;
        float d2 = kf[2].x * qf.x + kf[2].y * qf.y + kf[2].z * qf.z + kf[2].w * qf.w;
        float d3 = kf[3].x * qf.x + kf[3].y * qf.y + kf[3].z * qf.z + kf[3].w * qf.w;
#pragma unroll
        for (int o = 16; o; o >>= 1) {
            d0 += __shfl_xor_sync(0xffffffffu, d0, o);
            d1 += __shfl_xor_sync(0xffffffffu, d1, o);
            d2 += __shfl_xor_sync(0xffffffffu, d2, o);
            d3 += __shfl_xor_sync(0xffffffffu, d3, o);
        }
        d0 *= SCALE_F; d1 *= SCALE_F; d2 *= SCALE_F; d3 *= SCALE_F;
        if (lane == 0) {
            const int i = tb - t0;
            s_scores[i] = d0;
            if (tb + 1 < t1) s_scores[i + 1] = d1;
            if (tb + 2 < t1) s_scores[i + 2] = d2;
            if (tb + 3 < t1) s_scores[i + 3] = d3;
        }
        wmax = fmaxf(wmax, d0);
        if (tb + 1 < t1) wmax = fmaxf(wmax, d1);
        if (tb + 2 < t1) wmax = fmaxf(wmax, d2);
        if (tb + 3 < t1) wmax = fmaxf(wmax, d3);
    }
    if (lane == 0) s_red[warp] = wmax;
    __syncthreads();
    const float m = fmaxf(fmaxf(s_red[0], s_red[1]), fmaxf(s_red[2], s_red[3]));
    __syncthreads();

    // ---- Pass 2: exp + sum ----
    float lsum = 0.0f;
    for (int i = tid; i < n; i += 128) {
        float p = __expf(s_scores[i] - m);
        s_scores[i] = p;
        lsum += p;
    }
#pragma unroll
    for (int o = 16; o; o >>= 1)
        lsum += __shfl_xor_sync(0xffffffffu, lsum, o);
    if (lane == 0) s_red[warp] = lsum;
    __syncthreads();
    const float ltot = s_red[0] + s_red[1] + s_red[2] + s_red[3];

    // ---- Pass 3: weighted V, 4 tokens per warp per iteration ----
    float4 acc = make_float4(0.f, 0.f, 0.f, 0.f);
    for (int tb = t0 + warp * 4; tb < t1; tb += 16) {
        float4 vf[4];
        float  p[4];
#pragma unroll
        for (int u = 0; u < 4; u++) {
            const int t = tb + u;
            if (t < t1) {
                const int phys = s_bt[t >> 6];
                vf[u] = *(const float4*)(V + ((size_t)phys * BLOCK_SZ + (t & 63)) * HIDDEN + hoff);
                p[u]  = s_scores[t - t0];
            } else {
                vf[u] = make_float4(0.f, 0.f, 0.f, 0.f);
                p[u]  = 0.0f;
            }
        }
#pragma unroll
        for (int u = 0; u < 4; u++) {
            acc.x = fmaf(p[u], vf[u].x, acc.x);
            acc.y = fmaf(p[u], vf[u].y, acc.y);
            acc.z = fmaf(p[u], vf[u].z, acc.z);
            acc.w = fmaf(p[u], vf[u].w, acc.w);
        }
    }
    *(float4*)&s_acc[warp][lane * 4] = acc;
    __syncthreads();

    part_o[(size_t)pidx * HEAD_DIM + tid] =
        s_acc[0][tid] + s_acc[1][tid] + s_acc[2][tid] + s_acc[3][tid];
    if (tid == 0) part_ml[pidx] = make_float2(m, ltot);
}

// Combine SPLITS partials via log-sum-exp. grid (64*16), 128 threads.
__global__ __launch_bounds__(128)
void attn_combine_kernel(const float*  __restrict__ part_o,
                         const float2* __restrict__ part_ml,
                         float* __restrict__ out) {
    const int sh  = blockIdx.x;
    const int tid = threadIdx.x;

    float2 ml[SPLITS];
#pragma unroll
    for (int i = 0; i < SPLITS; i++) ml[i] = part_ml[sh * SPLITS + i];

    float M = -1e30f;
#pragma unroll
    for (int i = 0; i < SPLITS; i++) M = fmaxf(M, ml[i].x);

    float L = 0.0f, o = 0.0f;
#pragma unroll
    for (int i = 0; i < SPLITS; i++) {
        const float w = __expf(ml[i].x - M);
        L += w * ml[i].y;
        o = fmaf(w, part_o[(size_t)(sh * SPLITS + i) * HEAD_DIM + tid], o);
    }

    const int seq = sh >> 4, head = sh & 15;
    out[(size_t)seq * HIDDEN + head * HEAD_DIM + tid] = o / L;
}

// ---------------------------------------------------------------------------
extern "C" void kernel_launch(void* const* d_in, const int* in_sizes, int n_in,
                              void* d_out, int out_size) {
    const float* hs     = (const float*)d_in[0];
    const float* kv     = (const float*)d_in[1];
    const float* W_attn = (const float*)d_in[2];
    const float* b_attn = (const float*)d_in[3];
    const float* W_proj = (const float*)d_in[4];
    const float* b_proj = (const float*)d_in[5];
    const int*   bt     = (const int*)d_in[6];
    const int*   slen   = (const int*)d_in[7];
    float*       out    = (float*)d_out;

    float  *qp = nullptr, *ap = nullptr, *pp = nullptr, *po = nullptr;
    float2 *pml = nullptr;
    cudaGetSymbolAddress((void**)&qp,  g_q);
    cudaGetSymbolAddress((void**)&ap,  g_attn);
    cudaGetSymbolAddress((void**)&pp,  g_part);
    cudaGetSymbolAddress((void**)&po,  g_po);
    cudaGetSymbolAddress((void**)&pml, g_pml);

    const dim3 gemm_grid(HIDDEN / 512, NUM_SEQS / 8, KCHUNKS);
    const int  red_ctas = (NUM_SEQS * HIDDEN / 4 + 255) / 256;

    // Q projection (only first HIDDEN cols of W_attn are used)
    gemm_splitk_kernel<<<gemm_grid, 128>>>(hs, W_attn, 3 * HIDDEN, pp);
    gemm_reduce_kernel<<<red_ctas, 256>>>(pp, b_attn, qp);

    // Paged attention, split-KV
    attn_partial_kernel<<<dim3(NUM_SEQS, NUM_HEADS, SPLITS), 128>>>(qp, kv, bt, slen, po, pml);
    attn_combine_kernel<<<NUM_SEQS * NUM_HEADS, 128>>>(po, pml, ap);

    // Output projection
    gemm_splitk_kernel<<<gemm_grid, 128>>>(ap, W_proj, HIDDEN, pp);
    gemm_reduce_kernel<<<red_ctas, 256>>>(pp, b_proj, out);
}